// round 16
// baseline (speedup 1.0000x reference)
#include <cuda_runtime.h>

#define BB   16
#define HWN  4096
#define EPSV 1e-5f

typedef unsigned long long u64;

// ---------------- packed f32x2 helpers ----------------
__device__ __forceinline__ u64 pack2(float lo, float hi) {
    u64 r; asm("mov.b64 %0, {%1, %2};" : "=l"(r) : "f"(lo), "f"(hi)); return r;
}
__device__ __forceinline__ u64 dup2(float v) {
    u64 r; asm("mov.b64 %0, {%1, %1};" : "=l"(r) : "f"(v)); return r;
}
__device__ __forceinline__ void fma2(u64& d, u64 a, u64 b) {
    asm("fma.rn.f32x2 %0, %1, %2, %0;" : "+l"(d) : "l"(a), "l"(b));
}
__device__ __forceinline__ float2 unpk(u64 v) {
    float2 r; asm("mov.b64 {%0, %1}, %2;" : "=f"(r.x), "=f"(r.y) : "l"(v)); return r;
}

// ---------------- scratch ----------------
__device__ __align__(16) float g_xT[BB * HWN * 64];     // x as [b][h][w][c]
__device__ __align__(16) float g_offs[BB * 18 * HWN];   // offsets (NCHW)
__device__ __align__(16) float g_mid[BB * 64 * HWN];    // branch sum
__device__ __align__(16) float g_w1T[9 * 64 * 64];      // [kk][c][co]
__device__ __align__(16) float g_w3T[25 * 64 * 64];     // [tap][c][co]
__device__ __align__(16) float g_w2T[9 * 64 * 64];      // [tap][c][co]
__device__ __align__(16) float g_woffT[9 * 64 * 20];    // [tap][c][oc(18 pad 20)]

// ---------------------------------------------------------------------------
// K0: transpose x [b][c][h][w] -> g_xT [b][h][w][c]
// ---------------------------------------------------------------------------
__global__ __launch_bounds__(256) void transpose_kernel(const float* __restrict__ x) {
    __shared__ float tile[64 * 65];
    int b = blockIdx.x >> 6, h = blockIdx.x & 63;
    const float* src = x + (b * 64) * HWN + h * 64;
    for (int i = threadIdx.x; i < 4096; i += 256) {
        int c = i >> 6, w = i & 63;
        tile[c * 65 + w] = src[c * HWN + w];
    }
    __syncthreads();
    float* dst = g_xT + (b * HWN + h * 64) * 64;
    for (int i = threadIdx.x; i < 4096; i += 256) {
        int w = i >> 6, c = i & 63;
        dst[w * 64 + c] = tile[c * 65 + w];
    }
}

// ---------------------------------------------------------------------------
// K0b: weight relayouts
// ---------------------------------------------------------------------------
__global__ void prep_weights(const float* __restrict__ w1, const float* __restrict__ w3,
                             const float* __restrict__ w2, const float* __restrict__ woff) {
    int t = blockIdx.x * blockDim.x + threadIdx.x;
    int stride = gridDim.x * blockDim.x;
    for (int i = t; i < 9 * 4096; i += stride) {
        int kk = i >> 12, c = (i >> 6) & 63, co = i & 63;
        g_w1T[i] = w1[(co * 64 + c) * 9 + kk];
    }
    for (int i = t; i < 25 * 4096; i += stride) {
        int tap = i >> 12, c = (i >> 6) & 63, co = i & 63;
        g_w3T[i] = w3[(co * 64 + c) * 25 + tap];
    }
    for (int i = t; i < 9 * 4096; i += stride) {
        int tap = i >> 12, c = (i >> 6) & 63, co = i & 63;
        g_w2T[i] = w2[(co * 64 + c) * 9 + tap];
    }
    for (int i = t; i < 9 * 64 * 20; i += stride) {
        int tap = i / 1280, r = i % 1280, c = r / 20, oc = r % 20;
        g_woffT[i] = (oc < 18) ? woff[(oc * 64 + c) * 9 + tap] : 0.f;
    }
}

// ---------------------------------------------------------------------------
// K1: offset conv 3x3 (64->18, pad 1) + bias  -> g_offs   (R13 verbatim)
// ---------------------------------------------------------------------------
#define OFF_SMEM ((6 * 64 * 68 + 9 * 64 * 20) * 4)
__global__ __launch_bounds__(256) void offset_kernel(const float* __restrict__ x,
                                                     const float* __restrict__ boff) {
    extern __shared__ float sm[];
    float* xs = sm;                 // [6][64][68], col = w_in + 1
    float* ws = sm + 6 * 64 * 68;   // [9][64][20]
    int b = blockIdx.x >> 4, hq = blockIdx.x & 15;
    int h0 = hq * 4;
    for (int i = threadIdx.x; i < 6 * 64 * 68; i += 256) xs[i] = 0.f;
    __syncthreads();
    for (int r = 0; r < 6; r++) {
        int gh = h0 - 1 + r;
        if ((unsigned)gh > 63u) continue;
        const float* src = x + b * 64 * HWN + gh * 64;
        for (int i = threadIdx.x; i < 4096; i += 256) {
            int c = i >> 6, w = i & 63;
            xs[(r * 64 + c) * 68 + 1 + w] = src[c * HWN + w];
        }
    }
    for (int i = threadIdx.x; i < 9 * 64 * 20; i += 256) ws[i] = g_woffT[i];
    __syncthreads();

    int r = threadIdx.x >> 6, w = threadIdx.x & 63;
    u64 acc[10];
#pragma unroll
    for (int j = 0; j < 10; j++) acc[j] = 0ull;

    for (int c = 0; c < 64; c++) {
#pragma unroll
        for (int ky = 0; ky < 3; ky++) {
            const float* xr = &xs[((r + ky) * 64 + c) * 68 + w];
            float x0 = xr[0], x1 = xr[1], x2 = xr[2];
#pragma unroll
            for (int kx = 0; kx < 3; kx++) {
                u64 ad = dup2(kx == 0 ? x0 : (kx == 1 ? x1 : x2));
                const ulonglong2* wp = (const ulonglong2*)&ws[((ky * 3 + kx) * 64 + c) * 20];
#pragma unroll
                for (int q = 0; q < 5; q++) {
                    ulonglong2 wv = wp[q];
                    fma2(acc[2 * q], ad, wv.x);
                    fma2(acc[2 * q + 1], ad, wv.y);
                }
            }
        }
    }
    int h = h0 + r;
#pragma unroll
    for (int i = 0; i < 9; i++) {
        float2 vv = unpk(acc[i]);
        int oc0 = 2 * i;
        g_offs[((b * 18 + oc0) * 64 + h) * 64 + w] = vv.x + __ldg(&boff[oc0]);
        g_offs[((b * 18 + oc0 + 1) * 64 + h) * 64 + w] = vv.y + __ldg(&boff[oc0 + 1]);
    }
}

// ---------------------------------------------------------------------------
// K2/K4: windowed conv GEMM, 128 threads, 8px x 4co tiles.  (R13 verbatim)
// ---------------------------------------------------------------------------
template <int K, int PAD, bool FINAL>
__global__ __launch_bounds__(128) void convgemm_kernel(
    const float* __restrict__ x, const float* __restrict__ gg,
    const float* __restrict__ bbp, const float* __restrict__ mm,
    const float* __restrict__ vv, float* __restrict__ outp) {
    extern __shared__ float xs[];  // [K][16][68], col = w_in + PAD
    const float* src = FINAL ? (const float*)g_mid : x;
    const float* wT  = FINAL ? (const float*)g_w2T : (const float*)g_w3T;
    int b = blockIdx.x >> 6, h = blockIdx.x & 63;
    int t = threadIdx.x;
    int tx = t & 15, ty = t >> 4;
    int co0 = tx * 4, px0 = ty * 8;

    u64 acc[8][2];
#pragma unroll
    for (int p = 0; p < 8; p++) { acc[p][0] = 0ull; acc[p][1] = 0ull; }

    for (int pass = 0; pass < 4; pass++) {
        __syncthreads();
        {
            float4 z4 = make_float4(0.f, 0.f, 0.f, 0.f);
            for (int i = t; i < K * 16 * 17; i += 128) ((float4*)xs)[i] = z4;
        }
        __syncthreads();
        for (int r = 0; r < K; r++) {
            int gh = h - PAD + r;
            if ((unsigned)gh > 63u) continue;
            const float* sp = src + (size_t)(b * 64 + pass * 16) * HWN + gh * 64;
            for (int i = t; i < 256; i += 128) {
                int cc = i >> 4, q = i & 15;
                float4 v4 = *(const float4*)(sp + cc * HWN + q * 4);
                float* d = &xs[(r * 16 + cc) * 68 + PAD + q * 4];
                d[0] = v4.x; d[1] = v4.y; d[2] = v4.z; d[3] = v4.w;
            }
        }
        __syncthreads();

        for (int cc = 0; cc < 16; cc++) {
            int c = pass * 16 + cc;
#pragma unroll
            for (int ky = 0; ky < K; ky++) {
                const float* rowp = &xs[(ky * 16 + cc) * 68 + px0];
                u64 wdup[K + 7];
                {
                    float4 t0 = *(const float4*)rowp;
                    float4 t1 = *(const float4*)(rowp + 4);
                    float4 t2 = *(const float4*)(rowp + 8);
                    float wf[12] = {t0.x, t0.y, t0.z, t0.w,
                                    t1.x, t1.y, t1.z, t1.w,
                                    t2.x, t2.y, t2.z, t2.w};
#pragma unroll
                    for (int j = 0; j < K + 7; j++) wdup[j] = dup2(wf[j]);
                }
#pragma unroll
                for (int kx = 0; kx < K; kx++) {
                    ulonglong2 wv = __ldg((const ulonglong2*)&wT[((size_t)(ky * K + kx) * 64 + c) * 64 + co0]);
#pragma unroll
                    for (int p = 0; p < 8; p++) {
                        fma2(acc[p][0], wdup[p + kx], wv.x);
                        fma2(acc[p][1], wdup[p + kx], wv.y);
                    }
                }
            }
        }
    }

    float ov[4][8];
#pragma unroll
    for (int p = 0; p < 8; p++) {
        float2 e0 = unpk(acc[p][0]);
        float2 e1 = unpk(acc[p][1]);
        ov[0][p] = e0.x; ov[1][p] = e0.y; ov[2][p] = e1.x; ov[3][p] = e1.y;
    }
#pragma unroll
    for (int j = 0; j < 4; j++) {
        int oc = co0 + j;
        float sc = __ldg(&gg[oc]) * rsqrtf(__ldg(&vv[oc]) + EPSV);
        float sh = __ldg(&bbp[oc]) - __ldg(&mm[oc]) * sc;
        size_t base = ((size_t)(b * 64 + oc) * 64 + h) * 64 + px0;
        if (FINAL) {
            float4 r0 = *(const float4*)(x + base);
            float4 r1 = *(const float4*)(x + base + 4);
            float4 o0, o1;
            o0.x = fmaxf(ov[j][0] * sc + sh + r0.x, 0.f);
            o0.y = fmaxf(ov[j][1] * sc + sh + r0.y, 0.f);
            o0.z = fmaxf(ov[j][2] * sc + sh + r0.z, 0.f);
            o0.w = fmaxf(ov[j][3] * sc + sh + r0.w, 0.f);
            o1.x = fmaxf(ov[j][4] * sc + sh + r1.x, 0.f);
            o1.y = fmaxf(ov[j][5] * sc + sh + r1.y, 0.f);
            o1.z = fmaxf(ov[j][6] * sc + sh + r1.z, 0.f);
            o1.w = fmaxf(ov[j][7] * sc + sh + r1.w, 0.f);
            *(float4*)(outp + base) = o0;
            *(float4*)(outp + base + 4) = o1;
        } else {
            float4 o0, o1;
            o0.x = fmaxf(ov[j][0] * sc + sh, 0.f);
            o0.y = fmaxf(ov[j][1] * sc + sh, 0.f);
            o0.z = fmaxf(ov[j][2] * sc + sh, 0.f);
            o0.w = fmaxf(ov[j][3] * sc + sh, 0.f);
            o1.x = fmaxf(ov[j][4] * sc + sh, 0.f);
            o1.y = fmaxf(ov[j][5] * sc + sh, 0.f);
            o1.z = fmaxf(ov[j][6] * sc + sh, 0.f);
            o1.w = fmaxf(ov[j][7] * sc + sh, 0.f);
            *(float4*)(g_mid + base) = o0;
            *(float4*)(g_mid + base + 4) = o1;
        }
    }
}

// ---------------------------------------------------------------------------
// K3: deformable conv 3x3 (64->64) + bn1 + relu, accumulate into g_mid.
// NEW: 2 output rows per block (grid 512, 256 thr). GEMM = 8px x 4co per
// thread with dup-hoisted weights: per c = 2 LDS.128 + 1 LDG.128 + 4 dup
// + 16 fma2. Gather keeps R5's coalescing pattern, looped over 2 rows.
// ---------------------------------------------------------------------------
#define APX 132   // A row stride: 128 positions + 4 pad
__global__ __launch_bounds__(256, 3) void deform_kernel(
    const float* __restrict__ g1, const float* __restrict__ b1,
    const float* __restrict__ m1, const float* __restrict__ v1) {
    __shared__ float A[64 * APX];    // [c][pos], pos = row*64 + ow
    __shared__ float cw[128 * 4];
    __shared__ int ci[128 * 4];

    int b = blockIdx.x >> 5, hp = blockIdx.x & 31;
    int h0 = hp * 2;
    int t = threadIdx.x;
    int tx = t & 15, ty = t >> 4;          // GEMM: co0 = tx*4; ty 0..15
    int co0 = tx * 4;
    int grow = ty >> 3, px0 = (ty & 7) * 8;  // row 0/1, px0 0..56
    int gpx = t >> 2, gcq = t & 3;           // gather: pixel 0..63, c-quad 0..3
    const float* xTb = g_xT + (size_t)b * HWN * 64;

    u64 acc[4][4];   // [px-pair][co]
#pragma unroll
    for (int p = 0; p < 4; p++)
#pragma unroll
        for (int j = 0; j < 4; j++) acc[p][j] = 0ull;

    for (int kk = 0; kk < 9; kk++) {
        __syncthreads();
        // --- coeff: 128 positions (2 rows x 64) ---
        if (t < 128) {
            int row = t >> 6, ow = t & 63;
            int h = h0 + row;
            int ky = kk / 3, kx = kk - ky * 3;
            float dy = g_offs[((b * 18 + 2 * kk) * 64 + h) * 64 + ow];
            float dx = g_offs[((b * 18 + 2 * kk + 1) * 64 + h) * 64 + ow];
            float ysf = (float)(h - 1 + ky) + dy;
            float xsf = (float)(ow - 1 + kx) + dx;
            float y0f = floorf(ysf), x0f = floorf(xsf);
            float wy1 = ysf - y0f, wx1 = xsf - x0f;
            float wy0 = 1.f - wy1, wx0 = 1.f - wx1;
            int y0 = (int)y0f, x0 = (int)x0f;
            int y1 = y0 + 1, x1 = x0 + 1;
            float vy0 = (y0 >= 0 && y0 < 64) ? 1.f : 0.f;
            float vy1 = (y1 >= 0 && y1 < 64) ? 1.f : 0.f;
            float vx0 = (x0 >= 0 && x0 < 64) ? 1.f : 0.f;
            float vx1 = (x1 >= 0 && x1 < 64) ? 1.f : 0.f;
            int yc0 = min(max(y0, 0), 63), yc1 = min(max(y1, 0), 63);
            int xc0 = min(max(x0, 0), 63), xc1 = min(max(x1, 0), 63);
            cw[t * 4 + 0] = wy0 * wx0 * vy0 * vx0;
            cw[t * 4 + 1] = wy0 * wx1 * vy0 * vx1;
            cw[t * 4 + 2] = wy1 * wx0 * vy1 * vx0;
            cw[t * 4 + 3] = wy1 * wx1 * vy1 * vx1;
            ci[t * 4 + 0] = (yc0 * 64 + xc0) * 64;
            ci[t * 4 + 1] = (yc0 * 64 + xc1) * 64;
            ci[t * 4 + 2] = (yc1 * 64 + xc0) * 64;
            ci[t * 4 + 3] = (yc1 * 64 + xc1) * 64;
        }
        __syncthreads();
        // --- gather: 2 row-halves, R5 pattern each ---
#pragma unroll
        for (int rh = 0; rh < 2; rh++) {
            int pos = rh * 64 + gpx;
            float q0 = cw[pos * 4 + 0], q1 = cw[pos * 4 + 1];
            float q2 = cw[pos * 4 + 2], q3 = cw[pos * 4 + 3];
            const float* p0 = xTb + ci[pos * 4 + 0];
            const float* p1 = xTb + ci[pos * 4 + 1];
            const float* p2 = xTb + ci[pos * 4 + 2];
            const float* p3 = xTb + ci[pos * 4 + 3];
#pragma unroll
            for (int i = 0; i < 4; i++) {
                int c0 = (gcq + 4 * i) * 4;
                float4 a0 = *(const float4*)(p0 + c0);
                float4 a1 = *(const float4*)(p1 + c0);
                float4 a2 = *(const float4*)(p2 + c0);
                float4 a3 = *(const float4*)(p3 + c0);
                A[(c0 + 0) * APX + pos] = a0.x * q0 + a1.x * q1 + a2.x * q2 + a3.x * q3;
                A[(c0 + 1) * APX + pos] = a0.y * q0 + a1.y * q1 + a2.y * q2 + a3.y * q3;
                A[(c0 + 2) * APX + pos] = a0.z * q0 + a1.z * q1 + a2.z * q2 + a3.z * q3;
                A[(c0 + 3) * APX + pos] = a0.w * q0 + a1.w * q1 + a2.w * q2 + a3.w * q3;
            }
        }
        __syncthreads();
        // --- GEMM: acc[px-pair][co] += A-pairs * dup(w) ---
        const float* wkk = g_w1T + kk * 4096;
        const int abase = grow * 64 + px0;
        for (int c = 0; c < 64; c++) {
            const float* ap = &A[c * APX + abase];
            ulonglong2 av0 = *(const ulonglong2*)ap;        // px pairs 0,1
            ulonglong2 av1 = *(const ulonglong2*)(ap + 4);  // px pairs 2,3
            float4 wq = __ldg((const float4*)&wkk[c * 64 + co0]);
            u64 wd0 = dup2(wq.x), wd1 = dup2(wq.y), wd2 = dup2(wq.z), wd3 = dup2(wq.w);
            fma2(acc[0][0], av0.x, wd0); fma2(acc[1][0], av0.y, wd0);
            fma2(acc[2][0], av1.x, wd0); fma2(acc[3][0], av1.y, wd0);
            fma2(acc[0][1], av0.x, wd1); fma2(acc[1][1], av0.y, wd1);
            fma2(acc[2][1], av1.x, wd1); fma2(acc[3][1], av1.y, wd1);
            fma2(acc[0][2], av0.x, wd2); fma2(acc[1][2], av0.y, wd2);
            fma2(acc[2][2], av1.x, wd2); fma2(acc[3][2], av1.y, wd2);
            fma2(acc[0][3], av0.x, wd3); fma2(acc[1][3], av0.y, wd3);
            fma2(acc[2][3], av1.x, wd3); fma2(acc[3][3], av1.y, wd3);
        }
    }

#pragma unroll
    for (int j = 0; j < 4; j++) {
        int oc = co0 + j;
        float sc = __ldg(&g1[oc]) * rsqrtf(__ldg(&v1[oc]) + EPSV);
        float sh = __ldg(&b1[oc]) - __ldg(&m1[oc]) * sc;
        float* mp = g_mid + ((size_t)(b * 64 + oc) * 64 + (h0 + grow)) * 64 + px0;
#pragma unroll
        for (int p = 0; p < 4; p++) {
            float2 e = unpk(acc[p][j]);
            mp[2 * p]     += fmaxf(e.x * sc + sh, 0.f);
            mp[2 * p + 1] += fmaxf(e.y * sc + sh, 0.f);
        }
    }
}

// ---------------------------------------------------------------------------
extern "C" void kernel_launch(void* const* d_in, const int* in_sizes, int n_in,
                              void* d_out, int out_size) {
    const float* x     = (const float*)d_in[0];
    const float* w_off = (const float*)d_in[1];
    const float* b_off = (const float*)d_in[2];
    const float* w1    = (const float*)d_in[3];
    const float* g1    = (const float*)d_in[4];
    const float* b1    = (const float*)d_in[5];
    const float* m1    = (const float*)d_in[6];
    const float* v1    = (const float*)d_in[7];
    const float* w3    = (const float*)d_in[8];
    const float* g3    = (const float*)d_in[9];
    const float* b3    = (const float*)d_in[10];
    const float* m3    = (const float*)d_in[11];
    const float* v3    = (const float*)d_in[12];
    const float* w2    = (const float*)d_in[13];
    const float* g2    = (const float*)d_in[14];
    const float* b2    = (const float*)d_in[15];
    const float* m2    = (const float*)d_in[16];
    const float* v2    = (const float*)d_in[17];
    float* out = (float*)d_out;

    const int SM_C5 = 5 * 16 * 68 * 4;  // 21760
    const int SM_C3 = 3 * 16 * 68 * 4;  // 13056

    cudaFuncSetAttribute(offset_kernel, cudaFuncAttributeMaxDynamicSharedMemorySize, OFF_SMEM);
    cudaFuncSetAttribute(convgemm_kernel<5, 2, false>, cudaFuncAttributeMaxDynamicSharedMemorySize, SM_C5);
    cudaFuncSetAttribute(convgemm_kernel<3, 1, true>,  cudaFuncAttributeMaxDynamicSharedMemorySize, SM_C3);

    dim3 grid(BB * 64);
    transpose_kernel<<<grid, 256>>>(x);
    prep_weights<<<128, 256>>>(w1, w3, w2, w_off);
    offset_kernel<<<BB * 16, 256, OFF_SMEM>>>(x, b_off);
    convgemm_kernel<5, 2, false><<<grid, 128, SM_C5>>>(x, g3, b3, m3, v3, out);
    deform_kernel<<<BB * 32, 256>>>(g1, b1, m1, v1);
    convgemm_kernel<3, 1, true><<<grid, 128, SM_C3>>>(x, g2, b2, m2, v2, out);
}

// round 17
// speedup vs baseline: 1.0565x; 1.0565x over previous
#include <cuda_runtime.h>

#define BB   16
#define HWN  4096
#define EPSV 1e-5f

typedef unsigned long long u64;

// ---------------- packed f32x2 helpers ----------------
__device__ __forceinline__ u64 pack2(float lo, float hi) {
    u64 r; asm("mov.b64 %0, {%1, %2};" : "=l"(r) : "f"(lo), "f"(hi)); return r;
}
__device__ __forceinline__ u64 dup2(float v) {
    u64 r; asm("mov.b64 %0, {%1, %1};" : "=l"(r) : "f"(v)); return r;
}
__device__ __forceinline__ void fma2(u64& d, u64 a, u64 b) {
    asm("fma.rn.f32x2 %0, %1, %2, %0;" : "+l"(d) : "l"(a), "l"(b));
}
__device__ __forceinline__ float2 unpk(u64 v) {
    float2 r; asm("mov.b64 {%0, %1}, %2;" : "=f"(r.x), "=f"(r.y) : "l"(v)); return r;
}

// ---------------- scratch ----------------
__device__ __align__(16) float g_xT[BB * HWN * 64];     // x as [b][h][w][c]
__device__ __align__(16) float g_offs[BB * 18 * HWN];   // offsets (NCHW)
__device__ __align__(16) float g_mid[BB * 64 * HWN];    // branch sum
__device__ __align__(16) float g_w1T[9 * 64 * 64];      // [kk][c][co]
__device__ __align__(16) float g_w3T[25 * 64 * 64];     // [tap][c][co]
__device__ __align__(16) float g_w2T[9 * 64 * 64];      // [tap][c][co]
__device__ __align__(16) float g_woffT[9 * 64 * 20];    // [tap][c][oc(18 pad 20)]

// ---------------------------------------------------------------------------
// K0: transpose x [b][c][h][w] -> g_xT [b][h][w][c]
// ---------------------------------------------------------------------------
__global__ __launch_bounds__(256) void transpose_kernel(const float* __restrict__ x) {
    __shared__ float tile[64 * 65];
    int b = blockIdx.x >> 6, h = blockIdx.x & 63;
    const float* src = x + (b * 64) * HWN + h * 64;
    for (int i = threadIdx.x; i < 4096; i += 256) {
        int c = i >> 6, w = i & 63;
        tile[c * 65 + w] = src[c * HWN + w];
    }
    __syncthreads();
    float* dst = g_xT + (b * HWN + h * 64) * 64;
    for (int i = threadIdx.x; i < 4096; i += 256) {
        int w = i >> 6, c = i & 63;
        dst[w * 64 + c] = tile[c * 65 + w];
    }
}

// ---------------------------------------------------------------------------
// K0b: weight relayouts
// ---------------------------------------------------------------------------
__global__ void prep_weights(const float* __restrict__ w1, const float* __restrict__ w3,
                             const float* __restrict__ w2, const float* __restrict__ woff) {
    int t = blockIdx.x * blockDim.x + threadIdx.x;
    int stride = gridDim.x * blockDim.x;
    for (int i = t; i < 9 * 4096; i += stride) {
        int kk = i >> 12, c = (i >> 6) & 63, co = i & 63;
        g_w1T[i] = w1[(co * 64 + c) * 9 + kk];
    }
    for (int i = t; i < 25 * 4096; i += stride) {
        int tap = i >> 12, c = (i >> 6) & 63, co = i & 63;
        g_w3T[i] = w3[(co * 64 + c) * 25 + tap];
    }
    for (int i = t; i < 9 * 4096; i += stride) {
        int tap = i >> 12, c = (i >> 6) & 63, co = i & 63;
        g_w2T[i] = w2[(co * 64 + c) * 9 + tap];
    }
    for (int i = t; i < 9 * 64 * 20; i += stride) {
        int tap = i / 1280, r = i % 1280, c = r / 20, oc = r % 20;
        g_woffT[i] = (oc < 18) ? woff[(oc * 64 + c) * 9 + tap] : 0.f;
    }
}

// ---------------------------------------------------------------------------
// K1: offset conv 3x3 (64->18, pad 1) + bias  -> g_offs   (R13 verbatim)
// ---------------------------------------------------------------------------
#define OFF_SMEM ((6 * 64 * 68 + 9 * 64 * 20) * 4)
__global__ __launch_bounds__(256) void offset_kernel(const float* __restrict__ x,
                                                     const float* __restrict__ boff) {
    extern __shared__ float sm[];
    float* xs = sm;                 // [6][64][68], col = w_in + 1
    float* ws = sm + 6 * 64 * 68;   // [9][64][20]
    int b = blockIdx.x >> 4, hq = blockIdx.x & 15;
    int h0 = hq * 4;
    for (int i = threadIdx.x; i < 6 * 64 * 68; i += 256) xs[i] = 0.f;
    __syncthreads();
    for (int r = 0; r < 6; r++) {
        int gh = h0 - 1 + r;
        if ((unsigned)gh > 63u) continue;
        const float* src = x + b * 64 * HWN + gh * 64;
        for (int i = threadIdx.x; i < 4096; i += 256) {
            int c = i >> 6, w = i & 63;
            xs[(r * 64 + c) * 68 + 1 + w] = src[c * HWN + w];
        }
    }
    for (int i = threadIdx.x; i < 9 * 64 * 20; i += 256) ws[i] = g_woffT[i];
    __syncthreads();

    int r = threadIdx.x >> 6, w = threadIdx.x & 63;
    u64 acc[10];
#pragma unroll
    for (int j = 0; j < 10; j++) acc[j] = 0ull;

    for (int c = 0; c < 64; c++) {
#pragma unroll
        for (int ky = 0; ky < 3; ky++) {
            const float* xr = &xs[((r + ky) * 64 + c) * 68 + w];
            float x0 = xr[0], x1 = xr[1], x2 = xr[2];
#pragma unroll
            for (int kx = 0; kx < 3; kx++) {
                u64 ad = dup2(kx == 0 ? x0 : (kx == 1 ? x1 : x2));
                const ulonglong2* wp = (const ulonglong2*)&ws[((ky * 3 + kx) * 64 + c) * 20];
#pragma unroll
                for (int q = 0; q < 5; q++) {
                    ulonglong2 wv = wp[q];
                    fma2(acc[2 * q], ad, wv.x);
                    fma2(acc[2 * q + 1], ad, wv.y);
                }
            }
        }
    }
    int h = h0 + r;
#pragma unroll
    for (int i = 0; i < 9; i++) {
        float2 vv = unpk(acc[i]);
        int oc0 = 2 * i;
        g_offs[((b * 18 + oc0) * 64 + h) * 64 + w] = vv.x + __ldg(&boff[oc0]);
        g_offs[((b * 18 + oc0 + 1) * 64 + h) * 64 + w] = vv.y + __ldg(&boff[oc0 + 1]);
    }
}

// ---------------------------------------------------------------------------
// K2/K4: windowed conv GEMM, 128 threads, 8px x 4co tiles.  (R13 verbatim)
// ---------------------------------------------------------------------------
template <int K, int PAD, bool FINAL>
__global__ __launch_bounds__(128) void convgemm_kernel(
    const float* __restrict__ x, const float* __restrict__ gg,
    const float* __restrict__ bbp, const float* __restrict__ mm,
    const float* __restrict__ vv, float* __restrict__ outp) {
    extern __shared__ float xs[];  // [K][16][68], col = w_in + PAD
    const float* src = FINAL ? (const float*)g_mid : x;
    const float* wT  = FINAL ? (const float*)g_w2T : (const float*)g_w3T;
    int b = blockIdx.x >> 6, h = blockIdx.x & 63;
    int t = threadIdx.x;
    int tx = t & 15, ty = t >> 4;
    int co0 = tx * 4, px0 = ty * 8;

    u64 acc[8][2];
#pragma unroll
    for (int p = 0; p < 8; p++) { acc[p][0] = 0ull; acc[p][1] = 0ull; }

    for (int pass = 0; pass < 4; pass++) {
        __syncthreads();
        {
            float4 z4 = make_float4(0.f, 0.f, 0.f, 0.f);
            for (int i = t; i < K * 16 * 17; i += 128) ((float4*)xs)[i] = z4;
        }
        __syncthreads();
        for (int r = 0; r < K; r++) {
            int gh = h - PAD + r;
            if ((unsigned)gh > 63u) continue;
            const float* sp = src + (size_t)(b * 64 + pass * 16) * HWN + gh * 64;
            for (int i = t; i < 256; i += 128) {
                int cc = i >> 4, q = i & 15;
                float4 v4 = *(const float4*)(sp + cc * HWN + q * 4);
                float* d = &xs[(r * 16 + cc) * 68 + PAD + q * 4];
                d[0] = v4.x; d[1] = v4.y; d[2] = v4.z; d[3] = v4.w;
            }
        }
        __syncthreads();

        for (int cc = 0; cc < 16; cc++) {
            int c = pass * 16 + cc;
#pragma unroll
            for (int ky = 0; ky < K; ky++) {
                const float* rowp = &xs[(ky * 16 + cc) * 68 + px0];
                u64 wdup[K + 7];
                {
                    float4 t0 = *(const float4*)rowp;
                    float4 t1 = *(const float4*)(rowp + 4);
                    float4 t2 = *(const float4*)(rowp + 8);
                    float wf[12] = {t0.x, t0.y, t0.z, t0.w,
                                    t1.x, t1.y, t1.z, t1.w,
                                    t2.x, t2.y, t2.z, t2.w};
#pragma unroll
                    for (int j = 0; j < K + 7; j++) wdup[j] = dup2(wf[j]);
                }
#pragma unroll
                for (int kx = 0; kx < K; kx++) {
                    ulonglong2 wv = __ldg((const ulonglong2*)&wT[((size_t)(ky * K + kx) * 64 + c) * 64 + co0]);
#pragma unroll
                    for (int p = 0; p < 8; p++) {
                        fma2(acc[p][0], wdup[p + kx], wv.x);
                        fma2(acc[p][1], wdup[p + kx], wv.y);
                    }
                }
            }
        }
    }

    float ov[4][8];
#pragma unroll
    for (int p = 0; p < 8; p++) {
        float2 e0 = unpk(acc[p][0]);
        float2 e1 = unpk(acc[p][1]);
        ov[0][p] = e0.x; ov[1][p] = e0.y; ov[2][p] = e1.x; ov[3][p] = e1.y;
    }
#pragma unroll
    for (int j = 0; j < 4; j++) {
        int oc = co0 + j;
        float sc = __ldg(&gg[oc]) * rsqrtf(__ldg(&vv[oc]) + EPSV);
        float sh = __ldg(&bbp[oc]) - __ldg(&mm[oc]) * sc;
        size_t base = ((size_t)(b * 64 + oc) * 64 + h) * 64 + px0;
        if (FINAL) {
            float4 r0 = *(const float4*)(x + base);
            float4 r1 = *(const float4*)(x + base + 4);
            float4 o0, o1;
            o0.x = fmaxf(ov[j][0] * sc + sh + r0.x, 0.f);
            o0.y = fmaxf(ov[j][1] * sc + sh + r0.y, 0.f);
            o0.z = fmaxf(ov[j][2] * sc + sh + r0.z, 0.f);
            o0.w = fmaxf(ov[j][3] * sc + sh + r0.w, 0.f);
            o1.x = fmaxf(ov[j][4] * sc + sh + r1.x, 0.f);
            o1.y = fmaxf(ov[j][5] * sc + sh + r1.y, 0.f);
            o1.z = fmaxf(ov[j][6] * sc + sh + r1.z, 0.f);
            o1.w = fmaxf(ov[j][7] * sc + sh + r1.w, 0.f);
            *(float4*)(outp + base) = o0;
            *(float4*)(outp + base + 4) = o1;
        } else {
            float4 o0, o1;
            o0.x = fmaxf(ov[j][0] * sc + sh, 0.f);
            o0.y = fmaxf(ov[j][1] * sc + sh, 0.f);
            o0.z = fmaxf(ov[j][2] * sc + sh, 0.f);
            o0.w = fmaxf(ov[j][3] * sc + sh, 0.f);
            o1.x = fmaxf(ov[j][4] * sc + sh, 0.f);
            o1.y = fmaxf(ov[j][5] * sc + sh, 0.f);
            o1.z = fmaxf(ov[j][6] * sc + sh, 0.f);
            o1.w = fmaxf(ov[j][7] * sc + sh, 0.f);
            *(float4*)(g_mid + base) = o0;
            *(float4*)(g_mid + base + 4) = o1;
        }
    }
}

// ---------------------------------------------------------------------------
// K3: deformable conv 3x3 (64->64) + bn1 + relu, accumulate into g_mid.
// NEW: 2 output rows per block (grid 512, 256 thr). GEMM = 8px x 4co per
// thread with dup-hoisted weights: per c = 2 LDS.128 + 1 LDG.128 + 4 dup
// + 16 fma2. Gather keeps R5's coalescing pattern, looped over 2 rows.
// ---------------------------------------------------------------------------
#define APX 132   // A row stride: 128 positions + 4 pad
__global__ __launch_bounds__(256, 3) void deform_kernel(
    const float* __restrict__ g1, const float* __restrict__ b1,
    const float* __restrict__ m1, const float* __restrict__ v1) {
    __shared__ float A[64 * APX];    // [c][pos], pos = row*64 + ow
    __shared__ float cw[128 * 4];
    __shared__ int ci[128 * 4];

    int b = blockIdx.x >> 5, hp = blockIdx.x & 31;
    int h0 = hp * 2;
    int t = threadIdx.x;
    int tx = t & 15, ty = t >> 4;          // GEMM: co0 = tx*4; ty 0..15
    int co0 = tx * 4;
    int grow = ty >> 3, px0 = (ty & 7) * 8;  // row 0/1, px0 0..56
    int gpx = t >> 2, gcq = t & 3;           // gather: pixel 0..63, c-quad 0..3
    const float* xTb = g_xT + (size_t)b * HWN * 64;

    u64 acc[4][4];   // [px-pair][co]
#pragma unroll
    for (int p = 0; p < 4; p++)
#pragma unroll
        for (int j = 0; j < 4; j++) acc[p][j] = 0ull;

    for (int kk = 0; kk < 9; kk++) {
        __syncthreads();
        // --- coeff: 128 positions (2 rows x 64) ---
        if (t < 128) {
            int row = t >> 6, ow = t & 63;
            int h = h0 + row;
            int ky = kk / 3, kx = kk - ky * 3;
            float dy = g_offs[((b * 18 + 2 * kk) * 64 + h) * 64 + ow];
            float dx = g_offs[((b * 18 + 2 * kk + 1) * 64 + h) * 64 + ow];
            float ysf = (float)(h - 1 + ky) + dy;
            float xsf = (float)(ow - 1 + kx) + dx;
            float y0f = floorf(ysf), x0f = floorf(xsf);
            float wy1 = ysf - y0f, wx1 = xsf - x0f;
            float wy0 = 1.f - wy1, wx0 = 1.f - wx1;
            int y0 = (int)y0f, x0 = (int)x0f;
            int y1 = y0 + 1, x1 = x0 + 1;
            float vy0 = (y0 >= 0 && y0 < 64) ? 1.f : 0.f;
            float vy1 = (y1 >= 0 && y1 < 64) ? 1.f : 0.f;
            float vx0 = (x0 >= 0 && x0 < 64) ? 1.f : 0.f;
            float vx1 = (x1 >= 0 && x1 < 64) ? 1.f : 0.f;
            int yc0 = min(max(y0, 0), 63), yc1 = min(max(y1, 0), 63);
            int xc0 = min(max(x0, 0), 63), xc1 = min(max(x1, 0), 63);
            cw[t * 4 + 0] = wy0 * wx0 * vy0 * vx0;
            cw[t * 4 + 1] = wy0 * wx1 * vy0 * vx1;
            cw[t * 4 + 2] = wy1 * wx0 * vy1 * vx0;
            cw[t * 4 + 3] = wy1 * wx1 * vy1 * vx1;
            ci[t * 4 + 0] = (yc0 * 64 + xc0) * 64;
            ci[t * 4 + 1] = (yc0 * 64 + xc1) * 64;
            ci[t * 4 + 2] = (yc1 * 64 + xc0) * 64;
            ci[t * 4 + 3] = (yc1 * 64 + xc1) * 64;
        }
        __syncthreads();
        // --- gather: 2 row-halves, R5 pattern each ---
#pragma unroll
        for (int rh = 0; rh < 2; rh++) {
            int pos = rh * 64 + gpx;
            float q0 = cw[pos * 4 + 0], q1 = cw[pos * 4 + 1];
            float q2 = cw[pos * 4 + 2], q3 = cw[pos * 4 + 3];
            const float* p0 = xTb + ci[pos * 4 + 0];
            const float* p1 = xTb + ci[pos * 4 + 1];
            const float* p2 = xTb + ci[pos * 4 + 2];
            const float* p3 = xTb + ci[pos * 4 + 3];
#pragma unroll
            for (int i = 0; i < 4; i++) {
                int c0 = (gcq + 4 * i) * 4;
                float4 a0 = *(const float4*)(p0 + c0);
                float4 a1 = *(const float4*)(p1 + c0);
                float4 a2 = *(const float4*)(p2 + c0);
                float4 a3 = *(const float4*)(p3 + c0);
                A[(c0 + 0) * APX + pos] = a0.x * q0 + a1.x * q1 + a2.x * q2 + a3.x * q3;
                A[(c0 + 1) * APX + pos] = a0.y * q0 + a1.y * q1 + a2.y * q2 + a3.y * q3;
                A[(c0 + 2) * APX + pos] = a0.z * q0 + a1.z * q1 + a2.z * q2 + a3.z * q3;
                A[(c0 + 3) * APX + pos] = a0.w * q0 + a1.w * q1 + a2.w * q2 + a3.w * q3;
            }
        }
        __syncthreads();
        // --- GEMM: acc[px-pair][co] += A-pairs * dup(w) ---
        const float* wkk = g_w1T + kk * 4096;
        const int abase = grow * 64 + px0;
        for (int c = 0; c < 64; c++) {
            const float* ap = &A[c * APX + abase];
            ulonglong2 av0 = *(const ulonglong2*)ap;        // px pairs 0,1
            ulonglong2 av1 = *(const ulonglong2*)(ap + 4);  // px pairs 2,3
            float4 wq = __ldg((const float4*)&wkk[c * 64 + co0]);
            u64 wd0 = dup2(wq.x), wd1 = dup2(wq.y), wd2 = dup2(wq.z), wd3 = dup2(wq.w);
            fma2(acc[0][0], av0.x, wd0); fma2(acc[1][0], av0.y, wd0);
            fma2(acc[2][0], av1.x, wd0); fma2(acc[3][0], av1.y, wd0);
            fma2(acc[0][1], av0.x, wd1); fma2(acc[1][1], av0.y, wd1);
            fma2(acc[2][1], av1.x, wd1); fma2(acc[3][1], av1.y, wd1);
            fma2(acc[0][2], av0.x, wd2); fma2(acc[1][2], av0.y, wd2);
            fma2(acc[2][2], av1.x, wd2); fma2(acc[3][2], av1.y, wd2);
            fma2(acc[0][3], av0.x, wd3); fma2(acc[1][3], av0.y, wd3);
            fma2(acc[2][3], av1.x, wd3); fma2(acc[3][3], av1.y, wd3);
        }
    }

#pragma unroll
    for (int j = 0; j < 4; j++) {
        int oc = co0 + j;
        float sc = __ldg(&g1[oc]) * rsqrtf(__ldg(&v1[oc]) + EPSV);
        float sh = __ldg(&b1[oc]) - __ldg(&m1[oc]) * sc;
        float* mp = g_mid + ((size_t)(b * 64 + oc) * 64 + (h0 + grow)) * 64 + px0;
#pragma unroll
        for (int p = 0; p < 4; p++) {
            float2 e = unpk(acc[p][j]);
            mp[2 * p]     += fmaxf(e.x * sc + sh, 0.f);
            mp[2 * p + 1] += fmaxf(e.y * sc + sh, 0.f);
        }
    }
}

// ---------------------------------------------------------------------------
extern "C" void kernel_launch(void* const* d_in, const int* in_sizes, int n_in,
                              void* d_out, int out_size) {
    const float* x     = (const float*)d_in[0];
    const float* w_off = (const float*)d_in[1];
    const float* b_off = (const float*)d_in[2];
    const float* w1    = (const float*)d_in[3];
    const float* g1    = (const float*)d_in[4];
    const float* b1    = (const float*)d_in[5];
    const float* m1    = (const float*)d_in[6];
    const float* v1    = (const float*)d_in[7];
    const float* w3    = (const float*)d_in[8];
    const float* g3    = (const float*)d_in[9];
    const float* b3    = (const float*)d_in[10];
    const float* m3    = (const float*)d_in[11];
    const float* v3    = (const float*)d_in[12];
    const float* w2    = (const float*)d_in[13];
    const float* g2    = (const float*)d_in[14];
    const float* b2    = (const float*)d_in[15];
    const float* m2    = (const float*)d_in[16];
    const float* v2    = (const float*)d_in[17];
    float* out = (float*)d_out;

    const int SM_C5 = 5 * 16 * 68 * 4;  // 21760
    const int SM_C3 = 3 * 16 * 68 * 4;  // 13056

    cudaFuncSetAttribute(offset_kernel, cudaFuncAttributeMaxDynamicSharedMemorySize, OFF_SMEM);
    cudaFuncSetAttribute(convgemm_kernel<5, 2, false>, cudaFuncAttributeMaxDynamicSharedMemorySize, SM_C5);
    cudaFuncSetAttribute(convgemm_kernel<3, 1, true>,  cudaFuncAttributeMaxDynamicSharedMemorySize, SM_C3);

    dim3 grid(BB * 64);
    transpose_kernel<<<grid, 256>>>(x);
    prep_weights<<<128, 256>>>(w1, w3, w2, w_off);
    offset_kernel<<<BB * 16, 256, OFF_SMEM>>>(x, b_off);
    convgemm_kernel<5, 2, false><<<grid, 128, SM_C5>>>(x, g3, b3, m3, v3, out);
    deform_kernel<<<BB * 32, 256>>>(g1, b1, m1, v1);
    convgemm_kernel<3, 1, true><<<grid, 128, SM_C3>>>(x, g2, b2, m2, v2, out);
}